// round 3
// baseline (speedup 1.0000x reference)
#include <cuda_runtime.h>

// SO(3) tensor product: for each triple t=(l1,l2,L):
//   p[i,j,M] = sum_{m,n} cg[M,n,m] * x_{l1}[i,m] * x_{l2}[j,n]
// Output: concat over L of concat over segments (triple order) of p.reshape(C*C, 2L+1).
//
// C = 512. 23 triples. Output = 25,952,256 fp32 (~104 MB) -> HBM-store-bound.

#define C 512
#define NTRIPLES 23
#define TI 8    // i rows per block
#define TJ 32   // j cols per block (= warp width -> contiguous stores)
#define NT 256  // threads per block
#define TILES_PER_TRIPLE ((C / TI) * (C / TJ))   // 64 * 16 = 1024

struct Args {
    const float* x[4];     // x_l : [C, 2l+1] row-major
    const float* cg[23];   // cg_t: [2L+1, 2l2+1, 2l1+1] row-major
    float* out;
};

// Per-triple metadata (triple order = _triples iteration order).
__constant__ int c_l1[NTRIPLES] = {0,0,0,0, 1,1,1,1,1,1,1,1, 2,2,2,2,2,2,2, 3,3,3,3};
__constant__ int c_l2[NTRIPLES] = {0,1,2,3, 1,1,1,2,2,2,3,3, 2,2,2,2,3,3,3, 3,3,3,3};
__constant__ int c_LL[NTRIPLES] = {0,1,2,3, 0,1,2,1,2,3,2,3, 0,1,2,3,1,2,3, 0,1,2,3};
// Output element offset of each triple's segment inside d_out
// (d_out = concat of out0,out1,out2,out3 flattened; within out_L segments are in
//  triple-iteration order, each segment = C*C*(2L+1) elements).
__constant__ int c_off[NTRIPLES] = {
            0,   // t0  (0,0,0) L0 s0
      1048576,   // t1  (0,1,1) L1 s0
      5767168,   // t2  (0,2,2) L2 s0
     14942208,   // t3  (0,3,3) L3 s0
       262144,   // t4  (1,1,0) L0 s1
      1835008,   // t5  (1,1,1) L1 s1
      7077888,   // t6  (1,1,2) L2 s1
      2621440,   // t7  (1,2,1) L1 s2
      8388608,   // t8  (1,2,2) L2 s2
     16777216,   // t9  (1,2,3) L3 s1
      9699328,   // t10 (1,3,2) L2 s3
     18612224,   // t11 (1,3,3) L3 s2
       524288,   // t12 (2,2,0) L0 s2
      3407872,   // t13 (2,2,1) L1 s3
     11010048,   // t14 (2,2,2) L2 s4
     20447232,   // t15 (2,2,3) L3 s3
      4194304,   // t16 (2,3,1) L1 s4
     12320768,   // t17 (2,3,2) L2 s5
     22282240,   // t18 (2,3,3) L3 s4
       786432,   // t19 (3,3,0) L0 s3
      4980736,   // t20 (3,3,1) L1 s5
     13631488,   // t21 (3,3,2) L2 s6
     24117248    // t22 (3,3,3) L3 s5
};

__global__ __launch_bounds__(NT) void tp_kernel(Args a) {
    const int t    = blockIdx.x >> 10;          // /1024 tiles per triple
    const int tile = blockIdx.x & 1023;
    const int i0 = (tile >> 4) * TI;            // 64 i-tiles
    const int j0 = (tile & 15) * TJ;            // 16 j-tiles

    const int l1 = c_l1[t], l2 = c_l2[t], LL = c_LL[t];
    const int n1 = 2 * l1 + 1;                  // size of m
    const int n2 = 2 * l2 + 1;                  // size of n
    const int nM = 2 * LL + 1;                  // size of M

    const float* __restrict__ xg1 = a.x[l1];
    const float* __restrict__ xg2 = a.x[l2];
    const float* __restrict__ cg  = a.cg[t];
    float* __restrict__ out = a.out + c_off[t];

    __shared__ float s_cg[343];                 // <= 7*7*7
    __shared__ float s_x2[TJ * 7];
    __shared__ float s_x1[TI * 7];
    __shared__ float s_y[TJ * 49];              // y[j][M][m], stride nM*n1 (odd)

    const int tid = threadIdx.x;

    // Stage cg / x tiles (all contiguous in gmem).
    const int ncg = nM * n2 * n1;
    for (int k = tid; k < ncg; k += NT) s_cg[k] = cg[k];
    const int nx2 = TJ * n2;
    for (int k = tid; k < nx2; k += NT) s_x2[k] = xg2[j0 * n2 + k];
    const int nx1 = TI * n1;
    for (int k = tid; k < nx1; k += NT) s_x1[k] = xg1[i0 * n1 + k];
    __syncthreads();

    // y[j,M,m] = sum_n cg[M,n,m] * x2[j,n]
    const int nym = nM * n1;                    // odd (product of odds)
    const int ny  = TJ * nym;
    for (int k = tid; k < ny; k += NT) {
        const int j = k / nym;
        const int r = k - j * nym;
        const int M = r / n1;
        const int m = r - M * n1;
        float acc = 0.f;
        #pragma unroll 4
        for (int n = 0; n < n2; n++)
            acc = fmaf(s_cg[(M * n2 + n) * n1 + m], s_x2[j * n2 + n], acc);
        s_y[k] = acc;
    }
    __syncthreads();

    // Each thread: one (i, j); lanes = consecutive j -> contiguous warp stores.
    const int il = tid >> 5;                    // 0..7
    const int jl = tid & 31;                    // 0..31

    float x1r[7];
    #pragma unroll
    for (int m = 0; m < 7; m++)
        x1r[m] = (m < n1) ? s_x1[il * n1 + m] : 0.f;

    const float* __restrict__ yrow = &s_y[jl * nym];   // conflict-free (odd stride)
    float* __restrict__ op = out + ((i0 + il) * C + (j0 + jl)) * nM;

    #pragma unroll 4
    for (int M = 0; M < nM; M++) {
        float acc = 0.f;
        #pragma unroll 4
        for (int m = 0; m < n1; m++)
            acc = fmaf(x1r[m], yrow[M * n1 + m], acc);
        op[M] = acc;
    }
}

extern "C" void kernel_launch(void* const* d_in, const int* in_sizes, int n_in,
                              void* d_out, int out_size) {
    Args a;
    for (int k = 0; k < 4; k++)  a.x[k]  = (const float*)d_in[k];
    for (int k = 0; k < 23; k++) a.cg[k] = (const float*)d_in[4 + k];
    a.out = (float*)d_out;

    tp_kernel<<<NTRIPLES * TILES_PER_TRIPLE, NT>>>(a);
}

// round 5
// speedup vs baseline: 2.1896x; 2.1896x over previous
#include <cuda_runtime.h>

// SO(3) tensor product: for each triple t=(l1,l2,L):
//   p[i,j,M] = sum_{m,n} cg[M,n,m] * x_{l1}[i,m] * x_{l2}[j,n]
// Output: concat over L of segments (triple order), each p.reshape(C*C, 2L+1).
//
// R3 finding: issue/ALU-bound (alu=60%, issue=91%) due to runtime loop bounds.
// Fix: full template specialization per triple + 4 i-rows per thread reusing a
// register-cached y-row.

#define C 512
#define NTRIPLES 23
#define NT 256
#define TI 32                 // i rows per block (8 warps x IPT=4)
#define TJ 32                 // j cols per block (lane -> contiguous stores)
#define IPT 4
#define TILES_PER_TRIPLE ((C / TI) * (C / TJ))   // 16 * 16 = 256

struct Args {
    const float* x[4];     // x_l : [C, 2l+1] row-major
    const float* cg[23];   // cg_t: [2L+1, 2l2+1, 2l1+1] row-major
    float* out;
};

// Output element offset of each triple's segment inside d_out
// (concat over L, then triple-iteration order within each L).
__constant__ int c_off[NTRIPLES] = {
            0,   // t0  (0,0,0) L0 s0
      1048576,   // t1  (0,1,1) L1 s0
      5767168,   // t2  (0,2,2) L2 s0
     14942208,   // t3  (0,3,3) L3 s0
       262144,   // t4  (1,1,0) L0 s1
      1835008,   // t5  (1,1,1) L1 s1
      7077888,   // t6  (1,1,2) L2 s1
      2621440,   // t7  (1,2,1) L1 s2
      8388608,   // t8  (1,2,2) L2 s2
     16777216,   // t9  (1,2,3) L3 s1
      9699328,   // t10 (1,3,2) L2 s3
     18612224,   // t11 (1,3,3) L3 s2
       524288,   // t12 (2,2,0) L0 s2
      3407872,   // t13 (2,2,1) L1 s3
     11010048,   // t14 (2,2,2) L2 s4
     20447232,   // t15 (2,2,3) L3 s3
      4194304,   // t16 (2,3,1) L1 s4
     12320768,   // t17 (2,3,2) L2 s5
     22282240,   // t18 (2,3,3) L3 s4
       786432,   // t19 (3,3,0) L0 s3
      4980736,   // t20 (3,3,1) L1 s5
     13631488,   // t21 (3,3,2) L2 s6
     24117248    // t22 (3,3,3) L3 s5
};

template<int L1, int L2, int LM>
__device__ __forceinline__ void tp_impl(
    const float* __restrict__ xg1, const float* __restrict__ xg2,
    const float* __restrict__ cg,  float* __restrict__ out,
    int i0, int j0,
    float* __restrict__ s_cg, float* __restrict__ s_x2,
    float* __restrict__ s_x1, float* __restrict__ s_y)
{
    constexpr int N1  = 2 * L1 + 1;       // m
    constexpr int N2  = 2 * L2 + 1;       // n
    constexpr int NM  = 2 * LM + 1;       // M
    constexpr int NYM = NM * N1;          // odd -> conflict-free smem stride
    constexpr int NCG = NM * N2 * N1;

    const int tid = threadIdx.x;

    // Stage (contiguous gmem reads, tiny).
    for (int k = tid; k < NCG; k += NT)     s_cg[k] = cg[k];
    for (int k = tid; k < TJ * N2; k += NT) s_x2[k] = xg2[j0 * N2 + k];
    for (int k = tid; k < TI * N1; k += NT) s_x1[k] = xg1[i0 * N1 + k];
    __syncthreads();

    // y[j,M,m] = sum_n cg[M,n,m] * x2[j,n]  (fully unrolled, compile-time div)
    constexpr int NY = TJ * NYM;
    #pragma unroll
    for (int k0 = 0; k0 < NY; k0 += NT) {
        const int k = k0 + tid;
        if (NY % NT == 0 || k < NY) {
            const int j = k / NYM;
            const int r = k - j * NYM;
            const int M = r / N1;
            const int m = r - M * N1;
            float acc = 0.f;
            #pragma unroll
            for (int n = 0; n < N2; n++)
                acc = fmaf(s_cg[(M * N2 + n) * N1 + m], s_x2[j * N2 + n], acc);
            s_y[k] = acc;
        }
    }
    __syncthreads();

    const int il = tid >> 5;              // warp id 0..7
    const int jl = tid & 31;              // lane  = j within tile

    // Cache this lane's y-row in registers (stride NYM odd -> conflict-free).
    float yr[NYM];
    #pragma unroll
    for (int k = 0; k < NYM; k++) yr[k] = s_y[jl * NYM + k];

    #pragma unroll
    for (int ii = 0; ii < IPT; ii++) {
        const int ir = il + 8 * ii;       // row within tile
        float x1r[N1];
        #pragma unroll
        for (int m = 0; m < N1; m++) x1r[m] = s_x1[ir * N1 + m];

        float* __restrict__ op = out + ((i0 + ir) * C + (j0 + jl)) * NM;
        #pragma unroll
        for (int M = 0; M < NM; M++) {
            float acc = 0.f;
            #pragma unroll
            for (int m = 0; m < N1; m++)
                acc = fmaf(x1r[m], yr[M * N1 + m], acc);
            op[M] = acc;
        }
    }
}

__global__ __launch_bounds__(NT) void tp_kernel(Args a) {
    __shared__ float s_cg[343];
    __shared__ float s_x2[TJ * 7];
    __shared__ float s_x1[TI * 7];
    __shared__ float s_y[TJ * 49];

    const int t    = blockIdx.x >> 8;     // 256 tiles per triple
    const int tile = blockIdx.x & 255;
    const int i0 = (tile >> 4) * TI;
    const int j0 = (tile & 15) * TJ;

    float* out = a.out + c_off[t];

    #define CASE(T, A, B, L) \
        case T: tp_impl<A, B, L>(a.x[A], a.x[B], a.cg[T], out, i0, j0, \
                                 s_cg, s_x2, s_x1, s_y); break;
    switch (t) {
        CASE( 0, 0, 0, 0)
        CASE( 1, 0, 1, 1)
        CASE( 2, 0, 2, 2)
        CASE( 3, 0, 3, 3)
        CASE( 4, 1, 1, 0)
        CASE( 5, 1, 1, 1)
        CASE( 6, 1, 1, 2)
        CASE( 7, 1, 2, 1)
        CASE( 8, 1, 2, 2)
        CASE( 9, 1, 2, 3)
        CASE(10, 1, 3, 2)
        CASE(11, 1, 3, 3)
        CASE(12, 2, 2, 0)
        CASE(13, 2, 2, 1)
        CASE(14, 2, 2, 2)
        CASE(15, 2, 2, 3)
        CASE(16, 2, 3, 1)
        CASE(17, 2, 3, 2)
        CASE(18, 2, 3, 3)
        CASE(19, 3, 3, 0)
        CASE(20, 3, 3, 1)
        CASE(21, 3, 3, 2)
        CASE(22, 3, 3, 3)
    }
    #undef CASE
}

extern "C" void kernel_launch(void* const* d_in, const int* in_sizes, int n_in,
                              void* d_out, int out_size) {
    Args a;
    for (int k = 0; k < 4; k++)  a.x[k]  = (const float*)d_in[k];
    for (int k = 0; k < 23; k++) a.cg[k] = (const float*)d_in[4 + k];
    a.out = (float*)d_out;

    tp_kernel<<<NTRIPLES * TILES_PER_TRIPLE, NT>>>(a);
}

// round 8
// speedup vs baseline: 3.5551x; 1.6236x over previous
#include <cuda_runtime.h>

// SO(3) tensor product: for each triple t=(l1,l2,L):
//   p[i,j,M] = sum_{m,n} cg[M,n,m] * x_{l1}[i,m] * x_{l2}[j,n]
// Output: concat over L of segments (triple order), each p.reshape(C*C, 2L+1).
//
// R5 finding: L1-bound (61.5%) from scattered scalar STG (28B lane stride ->
// 7x wavefront amplification). Fix: smem-staged output tile + coalesced STG.128.
// R6 fix: s.p must be 16B-aligned for float4 LDS (was at offset 9436 -> trap).

#define C 512
#define NTRIPLES 23
#define NT 256
#define TI 32                 // i rows per block (8 warps x IPT=4)
#define TJ 32                 // j cols per block
#define IPT 4
#define TILES_PER_TRIPLE ((C / TI) * (C / TJ))   // 16 * 16 = 256

struct Args {
    const float* x[4];     // x_l : [C, 2l+1] row-major
    const float* cg[23];   // cg_t: [2L+1, 2l2+1, 2l1+1] row-major
    float* out;
};

// Output element offset of each triple's segment inside d_out.
__constant__ int c_off[NTRIPLES] = {
            0,   // t0  (0,0,0) L0 s0
      1048576,   // t1  (0,1,1) L1 s0
      5767168,   // t2  (0,2,2) L2 s0
     14942208,   // t3  (0,3,3) L3 s0
       262144,   // t4  (1,1,0) L0 s1
      1835008,   // t5  (1,1,1) L1 s1
      7077888,   // t6  (1,1,2) L2 s1
      2621440,   // t7  (1,2,1) L1 s2
      8388608,   // t8  (1,2,2) L2 s2
     16777216,   // t9  (1,2,3) L3 s1
      9699328,   // t10 (1,3,2) L2 s3
     18612224,   // t11 (1,3,3) L3 s2
       524288,   // t12 (2,2,0) L0 s2
      3407872,   // t13 (2,2,1) L1 s3
     11010048,   // t14 (2,2,2) L2 s4
     20447232,   // t15 (2,2,3) L3 s3
      4194304,   // t16 (2,3,1) L1 s4
     12320768,   // t17 (2,3,2) L2 s5
     22282240,   // t18 (2,3,3) L3 s4
       786432,   // t19 (3,3,0) L0 s3
      4980736,   // t20 (3,3,1) L1 s5
     13631488,   // t21 (3,3,2) L2 s6
     24117248    // t22 (3,3,3) L3 s5
};

struct alignas(16) Smem {
    alignas(16) float p[TI * TJ * 7];   // staged output tile (28 KB max), 16B-aligned
    float cg[343];
    float x2[TJ * 7];
    float x1[TI * 7];
    float y[TJ * 49];          // y[j][M][m], odd stride -> conflict-free
};

template<int L1, int L2, int LM>
__device__ __forceinline__ void tp_impl(
    const float* __restrict__ xg1, const float* __restrict__ xg2,
    const float* __restrict__ cg,  float* __restrict__ out,
    int i0, int j0, Smem& s)
{
    constexpr int N1  = 2 * L1 + 1;       // m
    constexpr int N2  = 2 * L2 + 1;       // n
    constexpr int NM  = 2 * LM + 1;       // M
    constexpr int NYM = NM * N1;          // odd -> conflict-free smem stride
    constexpr int NCG = NM * N2 * N1;

    const int tid = threadIdx.x;

    // Stage inputs (contiguous gmem reads, tiny).
    for (int k = tid; k < NCG; k += NT)     s.cg[k] = cg[k];
    for (int k = tid; k < TJ * N2; k += NT) s.x2[k] = xg2[j0 * N2 + k];
    for (int k = tid; k < TI * N1; k += NT) s.x1[k] = xg1[i0 * N1 + k];
    __syncthreads();

    // y[j,M,m] = sum_n cg[M,n,m] * x2[j,n]  (fully unrolled, const bounds)
    constexpr int NY = TJ * NYM;
    #pragma unroll
    for (int k0 = 0; k0 < NY; k0 += NT) {
        const int k = k0 + tid;
        if (NY % NT == 0 || k < NY) {
            const int j = k / NYM;
            const int r = k - j * NYM;
            const int M = r / N1;
            const int m = r - M * N1;
            float acc = 0.f;
            #pragma unroll
            for (int n = 0; n < N2; n++)
                acc = fmaf(s.cg[(M * N2 + n) * N1 + m], s.x2[j * N2 + n], acc);
            s.y[k] = acc;
        }
    }
    __syncthreads();

    const int il = tid >> 5;              // warp id 0..7
    const int jl = tid & 31;              // lane  = j within tile

    // Cache this lane's y-row in registers (odd stride -> conflict-free LDS).
    float yr[NYM];
    #pragma unroll
    for (int k = 0; k < NYM; k++) yr[k] = s.y[jl * NYM + k];

    // Compute p into the staged tile: s.p[(ir*TJ + jl)*NM + M].
    // STS lane stride = NM (odd) -> conflict-free.
    #pragma unroll
    for (int ii = 0; ii < IPT; ii++) {
        const int ir = il * IPT + ii;
        float x1r[N1];
        #pragma unroll
        for (int m = 0; m < N1; m++) x1r[m] = s.x1[ir * N1 + m];

        float* __restrict__ prow = &s.p[(ir * TJ + jl) * NM];
        #pragma unroll
        for (int M = 0; M < NM; M++) {
            float acc = 0.f;
            #pragma unroll
            for (int m = 0; m < N1; m++)
                acc = fmaf(x1r[m], yr[M * N1 + m], acc);
            prow[M] = acc;
        }
    }
    __syncthreads();

    // Coalesced copy: each tile i-row is a contiguous TJ*NM-float run in gmem
    // starting at ((i0+row)*C + j0)*NM  (multiple of 4 elements -> 16B aligned).
    constexpr int ROWF4 = (TJ * NM) / 4;          // 8*NM float4 per i-row
    constexpr int TOTF4 = TI * ROWF4;             // 256*NM
    const float4* __restrict__ sp4 = (const float4*)s.p;
    #pragma unroll
    for (int it = 0; it < TOTF4 / NT; it++) {
        const int k   = it * NT + tid;
        const int row = k / ROWF4;
        const int col = k - row * ROWF4;
        float4 v = sp4[k];
        *(float4*)&out[((i0 + row) * C + j0) * NM + col * 4] = v;
    }
}

__global__ __launch_bounds__(NT) void tp_kernel(Args a) {
    __shared__ Smem s;

    const int t    = blockIdx.x >> 8;     // 256 tiles per triple
    const int tile = blockIdx.x & 255;
    const int i0 = (tile >> 4) * TI;
    const int j0 = (tile & 15) * TJ;

    float* out = a.out + c_off[t];

    #define CASE(T, A, B, L) \
        case T: tp_impl<A, B, L>(a.x[A], a.x[B], a.cg[T], out, i0, j0, s); break;
    switch (t) {
        CASE( 0, 0, 0, 0)
        CASE( 1, 0, 1, 1)
        CASE( 2, 0, 2, 2)
        CASE( 3, 0, 3, 3)
        CASE( 4, 1, 1, 0)
        CASE( 5, 1, 1, 1)
        CASE( 6, 1, 1, 2)
        CASE( 7, 1, 2, 1)
        CASE( 8, 1, 2, 2)
        CASE( 9, 1, 2, 3)
        CASE(10, 1, 3, 2)
        CASE(11, 1, 3, 3)
        CASE(12, 2, 2, 0)
        CASE(13, 2, 2, 1)
        CASE(14, 2, 2, 2)
        CASE(15, 2, 2, 3)
        CASE(16, 2, 3, 1)
        CASE(17, 2, 3, 2)
        CASE(18, 2, 3, 3)
        CASE(19, 3, 3, 0)
        CASE(20, 3, 3, 1)
        CASE(21, 3, 3, 2)
        CASE(22, 3, 3, 3)
    }
    #undef CASE
}

extern "C" void kernel_launch(void* const* d_in, const int* in_sizes, int n_in,
                              void* d_out, int out_size) {
    Args a;
    for (int k = 0; k < 4; k++)  a.x[k]  = (const float*)d_in[k];
    for (int k = 0; k < 23; k++) a.cg[k] = (const float*)d_in[4 + k];
    a.out = (float*)d_out;

    tp_kernel<<<NTRIPLES * TILES_PER_TRIPLE, NT>>>(a);
}

// round 9
// speedup vs baseline: 3.8816x; 1.0919x over previous
#include <cuda_runtime.h>

// SO(3) tensor product: for each triple t=(l1,l2,L):
//   p[i,j,M] = sum_{m,n} cg[M,n,m] * x_{l1}[i,m] * x_{l2}[j,n]
// Output: concat over L of segments (triple order), each p.reshape(C*C, 2L+1).
//
// R5: L1-bound scattered STG -> smem-staged coalesced STG.128 (36.9us).
// R8 finding: latency-bound, occ=33% limited by regs=77 (yr[49] cache).
// Fix: M-outer loop (y-slice of N1 regs reused across IPT rows, x1 pre-cached)
//      + __launch_bounds__(256, 4) to guarantee 4 blocks/SM.

#define C 512
#define NTRIPLES 23
#define NT 256
#define TI 32                 // i rows per block (8 warps x IPT=4)
#define TJ 32                 // j cols per block
#define IPT 4
#define TILES_PER_TRIPLE ((C / TI) * (C / TJ))   // 16 * 16 = 256

struct Args {
    const float* x[4];     // x_l : [C, 2l+1] row-major
    const float* cg[23];   // cg_t: [2L+1, 2l2+1, 2l1+1] row-major
    float* out;
};

// Output element offset of each triple's segment inside d_out.
__constant__ int c_off[NTRIPLES] = {
            0,   // t0  (0,0,0) L0 s0
      1048576,   // t1  (0,1,1) L1 s0
      5767168,   // t2  (0,2,2) L2 s0
     14942208,   // t3  (0,3,3) L3 s0
       262144,   // t4  (1,1,0) L0 s1
      1835008,   // t5  (1,1,1) L1 s1
      7077888,   // t6  (1,1,2) L2 s1
      2621440,   // t7  (1,2,1) L1 s2
      8388608,   // t8  (1,2,2) L2 s2
     16777216,   // t9  (1,2,3) L3 s1
      9699328,   // t10 (1,3,2) L2 s3
     18612224,   // t11 (1,3,3) L3 s2
       524288,   // t12 (2,2,0) L0 s2
      3407872,   // t13 (2,2,1) L1 s3
     11010048,   // t14 (2,2,2) L2 s4
     20447232,   // t15 (2,2,3) L3 s3
      4194304,   // t16 (2,3,1) L1 s4
     12320768,   // t17 (2,3,2) L2 s5
     22282240,   // t18 (2,3,3) L3 s4
       786432,   // t19 (3,3,0) L0 s3
      4980736,   // t20 (3,3,1) L1 s5
     13631488,   // t21 (3,3,2) L2 s6
     24117248    // t22 (3,3,3) L3 s5
};

struct alignas(16) Smem {
    alignas(16) float p[TI * TJ * 7];   // staged output tile (28 KB max), 16B-aligned
    float cg[343];
    float x2[TJ * 7];
    float x1[TI * 7];
    float y[TJ * 49];          // y[j][M][m], odd stride -> conflict-free
};

template<int L1, int L2, int LM>
__device__ __forceinline__ void tp_impl(
    const float* __restrict__ xg1, const float* __restrict__ xg2,
    const float* __restrict__ cg,  float* __restrict__ out,
    int i0, int j0, Smem& s)
{
    constexpr int N1  = 2 * L1 + 1;       // m
    constexpr int N2  = 2 * L2 + 1;       // n
    constexpr int NM  = 2 * LM + 1;       // M
    constexpr int NYM = NM * N1;          // odd -> conflict-free smem stride
    constexpr int NCG = NM * N2 * N1;

    const int tid = threadIdx.x;

    // Stage inputs (contiguous gmem reads, tiny).
    for (int k = tid; k < NCG; k += NT)     s.cg[k] = cg[k];
    for (int k = tid; k < TJ * N2; k += NT) s.x2[k] = xg2[j0 * N2 + k];
    for (int k = tid; k < TI * N1; k += NT) s.x1[k] = xg1[i0 * N1 + k];
    __syncthreads();

    // y[j,M,m] = sum_n cg[M,n,m] * x2[j,n]  (fully unrolled, const bounds)
    constexpr int NY = TJ * NYM;
    #pragma unroll
    for (int k0 = 0; k0 < NY; k0 += NT) {
        const int k = k0 + tid;
        if (NY % NT == 0 || k < NY) {
            const int j = k / NYM;
            const int r = k - j * NYM;
            const int M = r / N1;
            const int m = r - M * N1;
            float acc = 0.f;
            #pragma unroll
            for (int n = 0; n < N2; n++)
                acc = fmaf(s.cg[(M * N2 + n) * N1 + m], s.x2[j * N2 + n], acc);
            s.y[k] = acc;
        }
    }
    __syncthreads();

    const int il = tid >> 5;              // warp id 0..7
    const int jl = tid & 31;              // lane  = j within tile

    // Pre-cache x1 for this thread's IPT rows (broadcast LDS, cheap).
    float x1all[IPT][N1];
    #pragma unroll
    for (int ii = 0; ii < IPT; ii++)
        #pragma unroll
        for (int m = 0; m < N1; m++)
            x1all[ii][m] = s.x1[(il * IPT + ii) * N1 + m];

    // M-outer: load one y-slice (N1 floats), reuse across IPT rows.
    // Live regs: x1all (<=28) + yt (<=7) + bookkeeping -> fits 64.
    #pragma unroll
    for (int M = 0; M < NM; M++) {
        float yt[N1];
        #pragma unroll
        for (int m = 0; m < N1; m++)
            yt[m] = s.y[jl * NYM + M * N1 + m];   // odd lane stride -> no conflicts

        #pragma unroll
        for (int ii = 0; ii < IPT; ii++) {
            float acc = 0.f;
            #pragma unroll
            for (int m = 0; m < N1; m++)
                acc = fmaf(x1all[ii][m], yt[m], acc);
            // STS lane stride = NM (odd) -> conflict-free.
            s.p[((il * IPT + ii) * TJ + jl) * NM + M] = acc;
        }
    }
    __syncthreads();

    // Coalesced copy: each tile i-row is a contiguous TJ*NM-float run in gmem
    // starting at ((i0+row)*C + j0)*NM  (multiple of 4 elements -> 16B aligned).
    constexpr int ROWF4 = (TJ * NM) / 4;          // 8*NM float4 per i-row
    constexpr int TOTF4 = TI * ROWF4;             // 256*NM
    const float4* __restrict__ sp4 = (const float4*)s.p;
    #pragma unroll
    for (int it = 0; it < TOTF4 / NT; it++) {
        const int k   = it * NT + tid;
        const int row = k / ROWF4;
        const int col = k - row * ROWF4;
        float4 v = sp4[k];
        *(float4*)&out[((i0 + row) * C + j0) * NM + col * 4] = v;
    }
}

__global__ __launch_bounds__(NT, 4) void tp_kernel(Args a) {
    __shared__ Smem s;

    const int t    = blockIdx.x >> 8;     // 256 tiles per triple
    const int tile = blockIdx.x & 255;
    const int i0 = (tile >> 4) * TI;
    const int j0 = (tile & 15) * TJ;

    float* out = a.out + c_off[t];

    #define CASE(T, A, B, L) \
        case T: tp_impl<A, B, L>(a.x[A], a.x[B], a.cg[T], out, i0, j0, s); break;
    switch (t) {
        CASE( 0, 0, 0, 0)
        CASE( 1, 0, 1, 1)
        CASE( 2, 0, 2, 2)
        CASE( 3, 0, 3, 3)
        CASE( 4, 1, 1, 0)
        CASE( 5, 1, 1, 1)
        CASE( 6, 1, 1, 2)
        CASE( 7, 1, 2, 1)
        CASE( 8, 1, 2, 2)
        CASE( 9, 1, 2, 3)
        CASE(10, 1, 3, 2)
        CASE(11, 1, 3, 3)
        CASE(12, 2, 2, 0)
        CASE(13, 2, 2, 1)
        CASE(14, 2, 2, 2)
        CASE(15, 2, 2, 3)
        CASE(16, 2, 3, 1)
        CASE(17, 2, 3, 2)
        CASE(18, 2, 3, 3)
        CASE(19, 3, 3, 0)
        CASE(20, 3, 3, 1)
        CASE(21, 3, 3, 2)
        CASE(22, 3, 3, 3)
    }
    #undef CASE
}

extern "C" void kernel_launch(void* const* d_in, const int* in_sizes, int n_in,
                              void* d_out, int out_size) {
    Args a;
    for (int k = 0; k < 4; k++)  a.x[k]  = (const float*)d_in[k];
    for (int k = 0; k < 23; k++) a.cg[k] = (const float*)d_in[4 + k];
    a.out = (float*)d_out;

    tp_kernel<<<NTRIPLES * TILES_PER_TRIPLE, NT>>>(a);
}

// round 10
// speedup vs baseline: 4.4028x; 1.1343x over previous
#include <cuda_runtime.h>

// SO(3) tensor product: for each triple t=(l1,l2,L):
//   p[i,j,M] = sum_{m,n} cg[M,n,m] * x_{l1}[i,m] * x_{l2}[j,n]
// Output: concat over L of segments (triple order), each p.reshape(C*C, 2L+1).
//
// R5: smem-staged coalesced STG.128 (36.9us). R9: M-outer regs 56 (33.8us).
// R10: occupancy push — half-tile staging (p 28->14KB), warp-per-M y-phase
//      (cg reads become warp-broadcast), __launch_bounds__(256,6).

#define C 512
#define NTRIPLES 23
#define NT 256
#define TI 32                 // i rows per block
#define TJ 32                 // j cols per block
#define ROWS_H 16             // rows per staging half
#define TILES_PER_TRIPLE ((C / TI) * (C / TJ))   // 256

struct Args {
    const float* x[4];     // x_l : [C, 2l+1] row-major
    const float* cg[23];   // cg_t: [2L+1, 2l2+1, 2l1+1] row-major
    float* out;
};

// Output element offset of each triple's segment inside d_out.
__constant__ int c_off[NTRIPLES] = {
            0,   // t0  (0,0,0) L0 s0
      1048576,   // t1  (0,1,1) L1 s0
      5767168,   // t2  (0,2,2) L2 s0
     14942208,   // t3  (0,3,3) L3 s0
       262144,   // t4  (1,1,0) L0 s1
      1835008,   // t5  (1,1,1) L1 s1
      7077888,   // t6  (1,1,2) L2 s1
      2621440,   // t7  (1,2,1) L1 s2
      8388608,   // t8  (1,2,2) L2 s2
     16777216,   // t9  (1,2,3) L3 s1
      9699328,   // t10 (1,3,2) L2 s3
     18612224,   // t11 (1,3,3) L3 s2
       524288,   // t12 (2,2,0) L0 s2
      3407872,   // t13 (2,2,1) L1 s3
     11010048,   // t14 (2,2,2) L2 s4
     20447232,   // t15 (2,2,3) L3 s3
      4194304,   // t16 (2,3,1) L1 s4
     12320768,   // t17 (2,3,2) L2 s5
     22282240,   // t18 (2,3,3) L3 s4
       786432,   // t19 (3,3,0) L0 s3
      4980736,   // t20 (3,3,1) L1 s5
     13631488,   // t21 (3,3,2) L2 s6
     24117248    // t22 (3,3,3) L3 s5
};

struct alignas(16) Smem {
    alignas(16) float p[ROWS_H * TJ * 7];  // 14 KB staging half, 16B-aligned
    float cg[343];
    float x2[TJ * 7];
    float x1[TI * 7];
    float y[TJ * 49];          // y[j][M][m], odd stride -> conflict-free
};

template<int L1, int L2, int LM>
__device__ __forceinline__ void tp_impl(
    const float* __restrict__ xg1, const float* __restrict__ xg2,
    const float* __restrict__ cg,  float* __restrict__ out,
    int i0, int j0, Smem& s)
{
    constexpr int N1  = 2 * L1 + 1;       // m
    constexpr int N2  = 2 * L2 + 1;       // n
    constexpr int NM  = 2 * LM + 1;       // M
    constexpr int NYM = NM * N1;          // odd -> conflict-free smem stride
    constexpr int NCG = NM * N2 * N1;

    const int tid = threadIdx.x;
    const int il  = tid >> 5;             // warp id 0..7
    const int jl  = tid & 31;             // lane

    // Stage inputs (contiguous gmem reads, tiny).
    for (int k = tid; k < NCG; k += NT)     s.cg[k] = cg[k];
    for (int k = tid; k < TJ * N2; k += NT) s.x2[k] = xg2[j0 * N2 + k];
    for (int k = tid; k < TI * N1; k += NT) s.x1[k] = xg1[i0 * N1 + k];
    __syncthreads();

    // y-phase, warp-per-M: warp il computes y[:, M=il, :].
    // cg reads are lane-uniform (broadcast, 1 wavefront); x2 cached in regs.
    if (il < NM) {
        float x2r[N2];
        #pragma unroll
        for (int n = 0; n < N2; n++) x2r[n] = s.x2[jl * N2 + n];
        #pragma unroll
        for (int m = 0; m < N1; m++) {
            float acc = 0.f;
            #pragma unroll
            for (int n = 0; n < N2; n++)
                acc = fmaf(s.cg[(il * N2 + n) * N1 + m], x2r[n], acc);
            s.y[jl * NYM + il * N1 + m] = acc;   // odd stride -> conflict-free
        }
    }
    __syncthreads();

    // Two staging halves of ROWS_H=16 rows each; warp covers 2 rows per half.
    constexpr int ROWF4  = (TJ * NM) / 4;        // float4 per i-row
    constexpr int TOTF4H = ROWS_H * ROWF4;       // 128*NM per half
    const float4* __restrict__ sp4 = (const float4*)s.p;

    #pragma unroll
    for (int h = 0; h < 2; h++) {
        // --- compute half into s.p ---
        float x1r[2][N1];
        #pragma unroll
        for (int ii = 0; ii < 2; ii++)
            #pragma unroll
            for (int m = 0; m < N1; m++)
                x1r[ii][m] = s.x1[(h * ROWS_H + il * 2 + ii) * N1 + m];  // broadcast

        #pragma unroll
        for (int M = 0; M < NM; M++) {
            float yt[N1];
            #pragma unroll
            for (int m = 0; m < N1; m++)
                yt[m] = s.y[jl * NYM + M * N1 + m];   // odd lane stride, no conflicts

            #pragma unroll
            for (int ii = 0; ii < 2; ii++) {
                float acc = 0.f;
                #pragma unroll
                for (int m = 0; m < N1; m++)
                    acc = fmaf(x1r[ii][m], yt[m], acc);
                // STS lane stride = NM (odd) -> conflict-free.
                s.p[((il * 2 + ii) * TJ + jl) * NM + M] = acc;
            }
        }
        __syncthreads();

        // --- coalesced copy of the half ---
        #pragma unroll
        for (int it = 0; it < (TOTF4H + NT - 1) / NT; it++) {
            const int k = it * NT + tid;
            if (TOTF4H % NT == 0 || k < TOTF4H) {
                const int rl  = k / ROWF4;
                const int col = k - rl * ROWF4;
                float4 v = sp4[k];
                *(float4*)&out[((i0 + h * ROWS_H + rl) * C + j0) * NM + col * 4] = v;
            }
        }
        __syncthreads();   // next half reuses s.p
    }
}

__global__ __launch_bounds__(NT, 6) void tp_kernel(Args a) {
    __shared__ Smem s;

    const int t    = blockIdx.x >> 8;     // 256 tiles per triple
    const int tile = blockIdx.x & 255;
    const int i0 = (tile >> 4) * TI;
    const int j0 = (tile & 15) * TJ;

    float* out = a.out + c_off[t];

    #define CASE(T, A, B, L) \
        case T: tp_impl<A, B, L>(a.x[A], a.x[B], a.cg[T], out, i0, j0, s); break;
    switch (t) {
        CASE( 0, 0, 0, 0)
        CASE( 1, 0, 1, 1)
        CASE( 2, 0, 2, 2)
        CASE( 3, 0, 3, 3)
        CASE( 4, 1, 1, 0)
        CASE( 5, 1, 1, 1)
        CASE( 6, 1, 1, 2)
        CASE( 7, 1, 2, 1)
        CASE( 8, 1, 2, 2)
        CASE( 9, 1, 2, 3)
        CASE(10, 1, 3, 2)
        CASE(11, 1, 3, 3)
        CASE(12, 2, 2, 0)
        CASE(13, 2, 2, 1)
        CASE(14, 2, 2, 2)
        CASE(15, 2, 2, 3)
        CASE(16, 2, 3, 1)
        CASE(17, 2, 3, 2)
        CASE(18, 2, 3, 3)
        CASE(19, 3, 3, 0)
        CASE(20, 3, 3, 1)
        CASE(21, 3, 3, 2)
        CASE(22, 3, 3, 3)
    }
    #undef CASE
}

extern "C" void kernel_launch(void* const* d_in, const int* in_sizes, int n_in,
                              void* d_out, int out_size) {
    Args a;
    for (int k = 0; k < 4; k++)  a.x[k]  = (const float*)d_in[k];
    for (int k = 0; k < 23; k++) a.cg[k] = (const float*)d_in[4 + k];
    a.out = (float*)d_out;

    tp_kernel<<<NTRIPLES * TILES_PER_TRIPLE, NT>>>(a);
}

// round 11
// speedup vs baseline: 5.1820x; 1.1770x over previous
#include <cuda_runtime.h>

// SO(3) tensor product: for each triple t=(l1,l2,L):
//   p[i,j,M] = sum_{m,n} cg[M,n,m] * x_{l1}[i,m] * x_{l2}[j,n]
// Output: concat over L of segments (triple order), each p.reshape(C*C, 2L+1).
//
// R10 finding: L1-wavefront bound (67%); staging round-trip (STS+LDS of p) and
// scalar y reads cost ~4x the mandatory STG traffic.
// R11: direct-store scheme. s.y[j][M][m] == s.y[q*N1+m] with q=j*NM+M = output
// column order, so a thread owning output float4 column q4 loads its y data as
// N1 contiguous LDS.128 (conflict-free: chunk stride 16*N1 B, N1 odd), keeps it
// in registers, and iterates i-rows storing STG.128 directly. No p buffer.

#define C 512
#define NTRIPLES 23
#define NT 256
#define TI 32                 // i rows per block
#define TJ 32                 // j cols per block
#define TILES_PER_TRIPLE ((C / TI) * (C / TJ))   // 256

struct Args {
    const float* x[4];     // x_l : [C, 2l+1] row-major
    const float* cg[23];   // cg_t: [2L+1, 2l2+1, 2l1+1] row-major
    float* out;
};

// Output element offset of each triple's segment inside d_out.
__constant__ int c_off[NTRIPLES] = {
            0,   // t0  (0,0,0) L0 s0
      1048576,   // t1  (0,1,1) L1 s0
      5767168,   // t2  (0,2,2) L2 s0
     14942208,   // t3  (0,3,3) L3 s0
       262144,   // t4  (1,1,0) L0 s1
      1835008,   // t5  (1,1,1) L1 s1
      7077888,   // t6  (1,1,2) L2 s1
      2621440,   // t7  (1,2,1) L1 s2
      8388608,   // t8  (1,2,2) L2 s2
     16777216,   // t9  (1,2,3) L3 s1
      9699328,   // t10 (1,3,2) L2 s3
     18612224,   // t11 (1,3,3) L3 s2
       524288,   // t12 (2,2,0) L0 s2
      3407872,   // t13 (2,2,1) L1 s3
     11010048,   // t14 (2,2,2) L2 s4
     20447232,   // t15 (2,2,3) L3 s3
      4194304,   // t16 (2,3,1) L1 s4
     12320768,   // t17 (2,3,2) L2 s5
     22282240,   // t18 (2,3,3) L3 s4
       786432,   // t19 (3,3,0) L0 s3
      4980736,   // t20 (3,3,1) L1 s5
     13631488,   // t21 (3,3,2) L2 s6
     24117248    // t22 (3,3,3) L3 s5
};

struct alignas(16) Smem {
    alignas(16) float y[TJ * 49];  // y[q*N1+m], q=j*NM+M; 16B-aligned for LDS.128
    float cg[343];
    float x2[TJ * 7];
    float x1[TI * 7];
};

template<int L1, int L2, int LM>
__device__ __forceinline__ void tp_impl(
    const float* __restrict__ xg1, const float* __restrict__ xg2,
    const float* __restrict__ cg,  float* __restrict__ out,
    int i0, int j0, Smem& s)
{
    constexpr int N1  = 2 * L1 + 1;       // m
    constexpr int N2  = 2 * L2 + 1;       // n
    constexpr int NM  = 2 * LM + 1;       // M
    constexpr int NYM = NM * N1;
    constexpr int NCG = NM * N2 * N1;

    const int tid = threadIdx.x;
    const int il  = tid >> 5;             // warp id 0..7
    const int jl  = tid & 31;             // lane

    // Stage inputs (contiguous gmem reads, tiny).
    for (int k = tid; k < NCG; k += NT)     s.cg[k] = cg[k];
    for (int k = tid; k < TJ * N2; k += NT) s.x2[k] = xg2[j0 * N2 + k];
    for (int k = tid; k < TI * N1; k += NT) s.x1[k] = xg1[i0 * N1 + k];
    __syncthreads();

    // y-phase, warp-per-M: warp il computes y[:, M=il, :].
    // cg reads lane-uniform (broadcast); x2 cached in regs.
    if (il < NM) {
        float x2r[N2];
        #pragma unroll
        for (int n = 0; n < N2; n++) x2r[n] = s.x2[jl * N2 + n];
        #pragma unroll
        for (int m = 0; m < N1; m++) {
            float acc = 0.f;
            #pragma unroll
            for (int n = 0; n < N2; n++)
                acc = fmaf(s.cg[(il * N2 + n) * N1 + m], x2r[n], acc);
            s.y[jl * NYM + il * N1 + m] = acc;   // == s.y[(jl*NM+il)*N1 + m]
        }
    }
    __syncthreads();

    // Direct-store phase. Each used thread owns output float4 column q4
    // (covering q = q4*4 .. q4*4+3, q = jl*NM + M) and iterates i-rows.
    constexpr int G  = 8 * NM;            // float4 per i-row (TJ*NM/4)
    constexpr int RB = NT / G;            // row stride; threads >= G*RB idle
    const int q4 = tid % G;
    const int rb = tid / G;

    if (rb < RB) {
        // This thread's y data: 4 rows x N1 = contiguous [q4*4*N1, +4N1).
        // N1 LDS.128, 16B-aligned, conflict-free (chunk stride 16*N1, N1 odd).
        float yflat[4 * N1];
        const float4* __restrict__ yp = (const float4*)&s.y[q4 * 4 * N1];
        #pragma unroll
        for (int c = 0; c < N1; c++) {
            float4 v4 = yp[c];
            yflat[4 * c + 0] = v4.x;
            yflat[4 * c + 1] = v4.y;
            yflat[4 * c + 2] = v4.z;
            yflat[4 * c + 3] = v4.w;
        }

        for (int r = rb; r < TI; r += RB) {
            float x1r[N1];
            #pragma unroll
            for (int m = 0; m < N1; m++) x1r[m] = s.x1[r * N1 + m];  // broadcast

            float4 v;
            float acc;
            #pragma unroll
            for (int e = 0; e < 4; e++) {
                acc = 0.f;
                #pragma unroll
                for (int m = 0; m < N1; m++)
                    acc = fmaf(x1r[m], yflat[e * N1 + m], acc);
                ((float*)&v)[e] = acc;
            }
            // Contiguous, 16B-aligned: ((i0+r)*C + j0)*NM is a multiple of 4... q4*4 adds 4-elt granularity.
            *(float4*)&out[((i0 + r) * C + j0) * NM + q4 * 4] = v;
        }
    }
}

__global__ __launch_bounds__(NT, 5) void tp_kernel(Args a) {
    __shared__ Smem s;

    const int t    = blockIdx.x >> 8;     // 256 tiles per triple
    const int tile = blockIdx.x & 255;
    const int i0 = (tile >> 4) * TI;
    const int j0 = (tile & 15) * TJ;

    float* out = a.out + c_off[t];

    #define CASE(T, A, B, L) \
        case T: tp_impl<A, B, L>(a.x[A], a.x[B], a.cg[T], out, i0, j0, s); break;
    switch (t) {
        CASE( 0, 0, 0, 0)
        CASE( 1, 0, 1, 1)
        CASE( 2, 0, 2, 2)
        CASE( 3, 0, 3, 3)
        CASE( 4, 1, 1, 0)
        CASE( 5, 1, 1, 1)
        CASE( 6, 1, 1, 2)
        CASE( 7, 1, 2, 1)
        CASE( 8, 1, 2, 2)
        CASE( 9, 1, 2, 3)
        CASE(10, 1, 3, 2)
        CASE(11, 1, 3, 3)
        CASE(12, 2, 2, 0)
        CASE(13, 2, 2, 1)
        CASE(14, 2, 2, 2)
        CASE(15, 2, 2, 3)
        CASE(16, 2, 3, 1)
        CASE(17, 2, 3, 2)
        CASE(18, 2, 3, 3)
        CASE(19, 3, 3, 0)
        CASE(20, 3, 3, 1)
        CASE(21, 3, 3, 2)
        CASE(22, 3, 3, 3)
    }
    #undef CASE
}

extern "C" void kernel_launch(void* const* d_in, const int* in_sizes, int n_in,
                              void* d_out, int out_size) {
    Args a;
    for (int k = 0; k < 4; k++)  a.x[k]  = (const float*)d_in[k];
    for (int k = 0; k < 23; k++) a.cg[k] = (const float*)d_in[4 + k];
    a.out = (float*)d_out;

    tp_kernel<<<NTRIPLES * TILES_PER_TRIPLE, NT>>>(a);
}

// round 12
// speedup vs baseline: 5.2417x; 1.0115x over previous
#include <cuda_runtime.h>
#include <cstdint>

// SO(3) tensor product: for each triple t=(l1,l2,L):
//   p[i,j,M] = sum_{m,n} cg[M,n,m] * x_{l1}[i,m] * x_{l2}[j,n]
// Output: concat over L of segments (triple order), each p.reshape(C*C, 2L+1).
//
// R11: direct-store (25.3us), issue/L1 balanced ~53%.
// R12: packed f32x2 FFMA2 main loop (PTX fma.rn.f32x2): x1 staged as {v,v}
//      64-bit pairs (LDS.64 = ready packed operand), y packed per-thread once,
//      STG.128 from two b64 accumulators, pointer strength reduction.

#define C 512
#define NTRIPLES 23
#define NT 256
#define TI 32                 // i rows per block
#define TJ 32                 // j cols per block
#define TILES_PER_TRIPLE ((C / TI) * (C / TJ))   // 256

struct Args {
    const float* x[4];     // x_l : [C, 2l+1] row-major
    const float* cg[23];   // cg_t: [2L+1, 2l2+1, 2l1+1] row-major
    float* out;
};

// Output element offset of each triple's segment inside d_out.
__constant__ int c_off[NTRIPLES] = {
            0,   // t0  (0,0,0) L0 s0
      1048576,   // t1  (0,1,1) L1 s0
      5767168,   // t2  (0,2,2) L2 s0
     14942208,   // t3  (0,3,3) L3 s0
       262144,   // t4  (1,1,0) L0 s1
      1835008,   // t5  (1,1,1) L1 s1
      7077888,   // t6  (1,1,2) L2 s1
      2621440,   // t7  (1,2,1) L1 s2
      8388608,   // t8  (1,2,2) L2 s2
     16777216,   // t9  (1,2,3) L3 s1
      9699328,   // t10 (1,3,2) L2 s3
     18612224,   // t11 (1,3,3) L3 s2
       524288,   // t12 (2,2,0) L0 s2
      3407872,   // t13 (2,2,1) L1 s3
     11010048,   // t14 (2,2,2) L2 s4
     20447232,   // t15 (2,2,3) L3 s3
      4194304,   // t16 (2,3,1) L1 s4
     12320768,   // t17 (2,3,2) L2 s5
     22282240,   // t18 (2,3,3) L3 s4
       786432,   // t19 (3,3,0) L0 s3
      4980736,   // t20 (3,3,1) L1 s5
     13631488,   // t21 (3,3,2) L2 s6
     24117248    // t22 (3,3,3) L3 s5
};

// Packed f32x2 FMA: d = a*b + c (elementwise on {lo,hi}).
__device__ __forceinline__ void fma_f32x2(unsigned long long& d,
                                          unsigned long long a,
                                          unsigned long long b,
                                          unsigned long long c) {
    asm("fma.rn.f32x2 %0, %1, %2, %3;" : "=l"(d) : "l"(a), "l"(b), "l"(c));
}
__device__ __forceinline__ unsigned long long pack2(float lo, float hi) {
    unsigned long long r;
    asm("mov.b64 %0, {%1, %2};" : "=l"(r) : "f"(lo), "f"(hi));
    return r;
}

struct alignas(16) Smem {
    alignas(16) float y[TJ * 49];          // y[(j*NM+M)*N1 + m]; 16B for LDS.128
    alignas(8) unsigned long long x1pk[TI * 7];  // {v,v} duplicated pairs
    float cg[343];
    float x2[TJ * 7];
};

template<int L1, int L2, int LM>
__device__ __forceinline__ void tp_impl(
    const float* __restrict__ xg1, const float* __restrict__ xg2,
    const float* __restrict__ cg,  float* __restrict__ out,
    int i0, int j0, Smem& s)
{
    constexpr int N1  = 2 * L1 + 1;       // m
    constexpr int N2  = 2 * L2 + 1;       // n
    constexpr int NM  = 2 * LM + 1;       // M
    constexpr int NYM = NM * N1;
    constexpr int NCG = NM * N2 * N1;

    const int tid = threadIdx.x;
    const int il  = tid >> 5;             // warp id 0..7
    const int jl  = tid & 31;             // lane

    // Stage inputs (contiguous gmem reads, tiny). x1 duplicated into pairs.
    for (int k = tid; k < NCG; k += NT)     s.cg[k] = cg[k];
    for (int k = tid; k < TJ * N2; k += NT) s.x2[k] = xg2[j0 * N2 + k];
    for (int k = tid; k < TI * N1; k += NT) {
        const unsigned int u = __float_as_uint(xg1[i0 * N1 + k]);
        s.x1pk[k] = ((unsigned long long)u << 32) | u;
    }
    __syncthreads();

    // y-phase, warp-per-M: warp il computes y[:, M=il, :].
    if (il < NM) {
        float x2r[N2];
        #pragma unroll
        for (int n = 0; n < N2; n++) x2r[n] = s.x2[jl * N2 + n];
        #pragma unroll
        for (int m = 0; m < N1; m++) {
            float acc = 0.f;
            #pragma unroll
            for (int n = 0; n < N2; n++)
                acc = fmaf(s.cg[(il * N2 + n) * N1 + m], x2r[n], acc);
            s.y[jl * NYM + il * N1 + m] = acc;   // == s.y[(jl*NM+il)*N1 + m]
        }
    }
    __syncthreads();

    // Direct-store phase. Thread owns output float4 column q4 (elements
    // q4*4 .. q4*4+3 of each i-row) and iterates rows r = rb, rb+RB, ...
    constexpr int G  = 8 * NM;            // float4 per i-row (TJ*NM/4)
    constexpr int RB = NT / G;            // row stride
    const int q4 = tid % G;
    const int rb = tid / G;

    if (rb < RB) {
        // y block: contiguous [q4*4*N1, +4N1) -> N1 LDS.128, conflict-free.
        float yflat[4 * N1];
        const float4* __restrict__ yp = (const float4*)&s.y[q4 * 4 * N1];
        #pragma unroll
        for (int c = 0; c < N1; c++) {
            float4 v4 = yp[c];
            yflat[4 * c + 0] = v4.x;
            yflat[4 * c + 1] = v4.y;
            yflat[4 * c + 2] = v4.z;
            yflat[4 * c + 3] = v4.w;
        }
        // Pack once per thread: pair A = elements (0,1), pair B = (2,3).
        unsigned long long ypkA[N1], ypkB[N1];
        #pragma unroll
        for (int m = 0; m < N1; m++) {
            ypkA[m] = pack2(yflat[0 * N1 + m], yflat[1 * N1 + m]);
            ypkB[m] = pack2(yflat[2 * N1 + m], yflat[3 * N1 + m]);
        }

        float* __restrict__ op = out + ((i0 + rb) * C + j0) * NM + q4 * 4;
        constexpr int STEP = 0 + 0;  // placeholder to keep constexpr section tidy
        (void)STEP;
        const long long step = (long long)RB * C * NM;

        for (int r = rb; r < TI; r += RB) {
            unsigned long long accA = 0ull, accB = 0ull;   // {0.f,0.f}
            #pragma unroll
            for (int m = 0; m < N1; m++) {
                const unsigned long long xp = s.x1pk[r * N1 + m];  // LDS.64 packed
                fma_f32x2(accA, xp, ypkA[m], accA);
                fma_f32x2(accB, xp, ypkB[m], accB);
            }
            // Single STG.128 from the two b64 accumulators (16B aligned).
            ulonglong2 v; v.x = accA; v.y = accB;
            *(ulonglong2*)op = v;
            op += step;
        }
    }
}

__global__ __launch_bounds__(NT, 5) void tp_kernel(Args a) {
    __shared__ Smem s;

    const int t    = blockIdx.x >> 8;     // 256 tiles per triple
    const int tile = blockIdx.x & 255;
    const int i0 = (tile >> 4) * TI;
    const int j0 = (tile & 15) * TJ;

    float* out = a.out + c_off[t];

    #define CASE(T, A, B, L) \
        case T: tp_impl<A, B, L>(a.x[A], a.x[B], a.cg[T], out, i0, j0, s); break;
    switch (t) {
        CASE( 0, 0, 0, 0)
        CASE( 1, 0, 1, 1)
        CASE( 2, 0, 2, 2)
        CASE( 3, 0, 3, 3)
        CASE( 4, 1, 1, 0)
        CASE( 5, 1, 1, 1)
        CASE( 6, 1, 1, 2)
        CASE( 7, 1, 2, 1)
        CASE( 8, 1, 2, 2)
        CASE( 9, 1, 2, 3)
        CASE(10, 1, 3, 2)
        CASE(11, 1, 3, 3)
        CASE(12, 2, 2, 0)
        CASE(13, 2, 2, 1)
        CASE(14, 2, 2, 2)
        CASE(15, 2, 2, 3)
        CASE(16, 2, 3, 1)
        CASE(17, 2, 3, 2)
        CASE(18, 2, 3, 3)
        CASE(19, 3, 3, 0)
        CASE(20, 3, 3, 1)
        CASE(21, 3, 3, 2)
        CASE(22, 3, 3, 3)
    }
    #undef CASE
}

extern "C" void kernel_launch(void* const* d_in, const int* in_sizes, int n_in,
                              void* d_out, int out_size) {
    Args a;
    for (int k = 0; k < 4; k++)  a.x[k]  = (const float*)d_in[k];
    for (int k = 0; k < 23; k++) a.cg[k] = (const float*)d_in[4 + k];
    a.out = (float*)d_out;

    tp_kernel<<<NTRIPLES * TILES_PER_TRIPLE, NT>>>(a);
}

// round 13
// speedup vs baseline: 5.7977x; 1.1061x over previous
#include <cuda_runtime.h>
#include <cstdint>

// SO(3) tensor product: for each triple t=(l1,l2,L):
//   p[i,j,M] = sum_{m,n} cg[M,n,m] * x_{l1}[i,m] * x_{l2}[j,n]
// Output: concat over L of segments (triple order), each p.reshape(C*C, 2L+1).
//
// R11: direct-store (25.3us). R12: packed f32x2 (neutral; latency-bound).
// R13: TI=64 — halve block count (2944), amortize cg-stage/barriers/y-phase
//      over 2x the stores; y register block reused across 2x rows.

#define C 512
#define NTRIPLES 23
#define NT 256
#define TI 64                 // i rows per block
#define TJ 32                 // j cols per block
#define TILES_PER_TRIPLE ((C / TI) * (C / TJ))   // 8 * 16 = 128

struct Args {
    const float* x[4];     // x_l : [C, 2l+1] row-major
    const float* cg[23];   // cg_t: [2L+1, 2l2+1, 2l1+1] row-major
    float* out;
};

// Output element offset of each triple's segment inside d_out.
__constant__ int c_off[NTRIPLES] = {
            0,   // t0  (0,0,0) L0 s0
      1048576,   // t1  (0,1,1) L1 s0
      5767168,   // t2  (0,2,2) L2 s0
     14942208,   // t3  (0,3,3) L3 s0
       262144,   // t4  (1,1,0) L0 s1
      1835008,   // t5  (1,1,1) L1 s1
      7077888,   // t6  (1,1,2) L2 s1
      2621440,   // t7  (1,2,1) L1 s2
      8388608,   // t8  (1,2,2) L2 s2
     16777216,   // t9  (1,2,3) L3 s1
      9699328,   // t10 (1,3,2) L2 s3
     18612224,   // t11 (1,3,3) L3 s2
       524288,   // t12 (2,2,0) L0 s2
      3407872,   // t13 (2,2,1) L1 s3
     11010048,   // t14 (2,2,2) L2 s4
     20447232,   // t15 (2,2,3) L3 s3
      4194304,   // t16 (2,3,1) L1 s4
     12320768,   // t17 (2,3,2) L2 s5
     22282240,   // t18 (2,3,3) L3 s4
       786432,   // t19 (3,3,0) L0 s3
      4980736,   // t20 (3,3,1) L1 s5
     13631488,   // t21 (3,3,2) L2 s6
     24117248    // t22 (3,3,3) L3 s5
};

// Packed f32x2 FMA: d = a*b + c (elementwise on {lo,hi}).
__device__ __forceinline__ void fma_f32x2(unsigned long long& d,
                                          unsigned long long a,
                                          unsigned long long b,
                                          unsigned long long c) {
    asm("fma.rn.f32x2 %0, %1, %2, %3;" : "=l"(d) : "l"(a), "l"(b), "l"(c));
}
__device__ __forceinline__ unsigned long long pack2(float lo, float hi) {
    unsigned long long r;
    asm("mov.b64 %0, {%1, %2};" : "=l"(r) : "f"(lo), "f"(hi));
    return r;
}

struct alignas(16) Smem {
    alignas(16) float y[TJ * 49];                // y[(j*NM+M)*N1 + m]
    alignas(8) unsigned long long x1pk[TI * 7];  // {v,v} duplicated pairs
    float cg[343];
    float x2[TJ * 7];
};

template<int L1, int L2, int LM>
__device__ __forceinline__ void tp_impl(
    const float* __restrict__ xg1, const float* __restrict__ xg2,
    const float* __restrict__ cg,  float* __restrict__ out,
    int i0, int j0, Smem& s)
{
    constexpr int N1  = 2 * L1 + 1;       // m
    constexpr int N2  = 2 * L2 + 1;       // n
    constexpr int NM  = 2 * LM + 1;       // M
    constexpr int NYM = NM * N1;
    constexpr int NCG = NM * N2 * N1;

    const int tid = threadIdx.x;
    const int il  = tid >> 5;             // warp id 0..7
    const int jl  = tid & 31;             // lane

    // Stage inputs (contiguous gmem reads, tiny). x1 duplicated into pairs.
    for (int k = tid; k < NCG; k += NT)     s.cg[k] = cg[k];
    for (int k = tid; k < TJ * N2; k += NT) s.x2[k] = xg2[j0 * N2 + k];
    #pragma unroll
    for (int k0 = 0; k0 < TI * N1; k0 += NT) {
        const int k = k0 + tid;
        if ((TI * N1) % NT == 0 || k < TI * N1) {
            const unsigned int u = __float_as_uint(xg1[i0 * N1 + k]);
            s.x1pk[k] = ((unsigned long long)u << 32) | u;
        }
    }
    __syncthreads();

    // y-phase, warp-per-M: warp il computes y[:, M=il, :].
    if (il < NM) {
        float x2r[N2];
        #pragma unroll
        for (int n = 0; n < N2; n++) x2r[n] = s.x2[jl * N2 + n];
        #pragma unroll
        for (int m = 0; m < N1; m++) {
            float acc = 0.f;
            #pragma unroll
            for (int n = 0; n < N2; n++)
                acc = fmaf(s.cg[(il * N2 + n) * N1 + m], x2r[n], acc);
            s.y[jl * NYM + il * N1 + m] = acc;   // == s.y[(jl*NM+il)*N1 + m]
        }
    }
    __syncthreads();

    // Direct-store phase. Thread owns output float4 column q4 (elements
    // q4*4 .. q4*4+3 of each i-row) and iterates rows r = rb, rb+RB, ...
    constexpr int G  = 8 * NM;            // float4 per i-row (TJ*NM/4)
    constexpr int RB = NT / G;            // row stride
    const int q4 = tid % G;
    const int rb = tid / G;

    if (rb < RB) {
        // y block: contiguous [q4*4*N1, +4N1) -> N1 LDS.128, conflict-free.
        float yflat[4 * N1];
        const float4* __restrict__ yp = (const float4*)&s.y[q4 * 4 * N1];
        #pragma unroll
        for (int c = 0; c < N1; c++) {
            float4 v4 = yp[c];
            yflat[4 * c + 0] = v4.x;
            yflat[4 * c + 1] = v4.y;
            yflat[4 * c + 2] = v4.z;
            yflat[4 * c + 3] = v4.w;
        }
        // Pack once per thread: pair A = elements (0,1), pair B = (2,3).
        unsigned long long ypkA[N1], ypkB[N1];
        #pragma unroll
        for (int m = 0; m < N1; m++) {
            ypkA[m] = pack2(yflat[0 * N1 + m], yflat[1 * N1 + m]);
            ypkB[m] = pack2(yflat[2 * N1 + m], yflat[3 * N1 + m]);
        }

        float* __restrict__ op = out + ((i0 + rb) * C + j0) * NM + q4 * 4;
        const long long step = (long long)RB * C * NM;
        const unsigned long long* __restrict__ xp0 = &s.x1pk[rb * N1];

        #pragma unroll 2
        for (int r = rb; r < TI; r += RB) {
            unsigned long long accA = 0ull, accB = 0ull;   // {0.f,0.f}
            #pragma unroll
            for (int m = 0; m < N1; m++) {
                const unsigned long long xp = xp0[m];      // LDS.64 packed
                fma_f32x2(accA, xp, ypkA[m], accA);
                fma_f32x2(accB, xp, ypkB[m], accB);
            }
            ulonglong2 v; v.x = accA; v.y = accB;
            *(ulonglong2*)op = v;                          // STG.128, 16B aligned
            op  += step;
            xp0 += RB * N1;
        }
    }
}

__global__ __launch_bounds__(NT, 5) void tp_kernel(Args a) {
    __shared__ Smem s;

    const int t    = blockIdx.x >> 7;     // 128 tiles per triple
    const int tile = blockIdx.x & 127;
    const int i0 = (tile >> 4) * TI;      // 8 i-tiles
    const int j0 = (tile & 15) * TJ;      // 16 j-tiles

    float* out = a.out + c_off[t];

    #define CASE(T, A, B, L) \
        case T: tp_impl<A, B, L>(a.x[A], a.x[B], a.cg[T], out, i0, j0, s); break;
    switch (t) {
        CASE( 0, 0, 0, 0)
        CASE( 1, 0, 1, 1)
        CASE( 2, 0, 2, 2)
        CASE( 3, 0, 3, 3)
        CASE( 4, 1, 1, 0)
        CASE( 5, 1, 1, 1)
        CASE( 6, 1, 1, 2)
        CASE( 7, 1, 2, 1)
        CASE( 8, 1, 2, 2)
        CASE( 9, 1, 2, 3)
        CASE(10, 1, 3, 2)
        CASE(11, 1, 3, 3)
        CASE(12, 2, 2, 0)
        CASE(13, 2, 2, 1)
        CASE(14, 2, 2, 2)
        CASE(15, 2, 2, 3)
        CASE(16, 2, 3, 1)
        CASE(17, 2, 3, 2)
        CASE(18, 2, 3, 3)
        CASE(19, 3, 3, 0)
        CASE(20, 3, 3, 1)
        CASE(21, 3, 3, 2)
        CASE(22, 3, 3, 3)
    }
    #undef CASE
}

extern "C" void kernel_launch(void* const* d_in, const int* in_sizes, int n_in,
                              void* d_out, int out_size) {
    Args a;
    for (int k = 0; k < 4; k++)  a.x[k]  = (const float*)d_in[k];
    for (int k = 0; k < 23; k++) a.cg[k] = (const float*)d_in[4 + k];
    a.out = (float*)d_out;

    tp_kernel<<<NTRIPLES * TILES_PER_TRIPLE, NT>>>(a);
}

// round 16
// speedup vs baseline: 6.0015x; 1.0351x over previous
#include <cuda_runtime.h>
#include <cstdint>

// SO(3) tensor product: for each triple t=(l1,l2,L):
//   p[i,j,M] = sum_{m,n} cg[M,n,m] * x_{l1}[i,m] * x_{l2}[j,n]
// Output: concat over L of segments (triple order), each p.reshape(C*C, 2L+1).
//
// R13: TI=64 direct-store, 22.6us, latency/tail-bound.
// R14: (1) LPT block order (NM=7 triples first -> short blocks in tail wave);
//      (2) x1pk padded to stride 8 -> 16B-aligned LDS.128 pair loads (7->4).

#define C 512
#define NTRIPLES 23
#define NT 256
#define TI 64                 // i rows per block
#define TJ 32                 // j cols per block
#define TILES_PER_TRIPLE ((C / TI) * (C / TJ))   // 8 * 16 = 128

struct Args {
    const float* x[4];     // x_l : [C, 2l+1] row-major
    const float* cg[23];   // cg_t: [2L+1, 2l2+1, 2l1+1] row-major
    float* out;
};

// Output element offset of each triple's segment inside d_out.
__constant__ int c_off[NTRIPLES] = {
            0,   // t0  (0,0,0) L0 s0
      1048576,   // t1  (0,1,1) L1 s0
      5767168,   // t2  (0,2,2) L2 s0
     14942208,   // t3  (0,3,3) L3 s0
       262144,   // t4  (1,1,0) L0 s1
      1835008,   // t5  (1,1,1) L1 s1
      7077888,   // t6  (1,1,2) L2 s1
      2621440,   // t7  (1,2,1) L1 s2
      8388608,   // t8  (1,2,2) L2 s2
     16777216,   // t9  (1,2,3) L3 s1
      9699328,   // t10 (1,3,2) L2 s3
     18612224,   // t11 (1,3,3) L3 s2
       524288,   // t12 (2,2,0) L0 s2
      3407872,   // t13 (2,2,1) L1 s3
     11010048,   // t14 (2,2,2) L2 s4
     20447232,   // t15 (2,2,3) L3 s3
      4194304,   // t16 (2,3,1) L1 s4
     12320768,   // t17 (2,3,2) L2 s5
     22282240,   // t18 (2,3,3) L3 s4
       786432,   // t19 (3,3,0) L0 s3
      4980736,   // t20 (3,3,1) L1 s5
     13631488,   // t21 (3,3,2) L2 s6
     24117248    // t22 (3,3,3) L3 s5
};

// LPT order: triples sorted by NM descending (7,5,3,1) -> long blocks first.
__constant__ int c_perm[NTRIPLES] = {
    3, 9, 11, 15, 18, 22,        // NM=7
    2, 6, 8, 10, 14, 17, 21,     // NM=5
    1, 5, 7, 13, 16, 20,         // NM=3
    0, 4, 12, 19                 // NM=1
};

// Packed f32x2 FMA: d = a*b + c (elementwise on {lo,hi}).
__device__ __forceinline__ void fma_f32x2(unsigned long long& d,
                                          unsigned long long a,
                                          unsigned long long b,
                                          unsigned long long c) {
    asm("fma.rn.f32x2 %0, %1, %2, %3;" : "=l"(d) : "l"(a), "l"(b), "l"(c));
}
__device__ __forceinline__ unsigned long long pack2(float lo, float hi) {
    unsigned long long r;
    asm("mov.b64 %0, {%1, %2};" : "=l"(r) : "f"(lo), "f"(hi));
    return r;
}

struct alignas(16) Smem {
    alignas(16) float y[TJ * 49];                  // y[(j*NM+M)*N1 + m]
    alignas(16) unsigned long long x1pk[TI * 8];   // {v,v} pairs, row stride 8 (64B-aligned rows)
    float cg[343];
    float x2[TJ * 7];
};

template<int L1, int L2, int LM>
__device__ __forceinline__ void tp_impl(
    const float* __restrict__ xg1, const float* __restrict__ xg2,
    const float* __restrict__ cg,  float* __restrict__ out,
    int i0, int j0, Smem& s)
{
    constexpr int N1  = 2 * L1 + 1;       // m
    constexpr int N2  = 2 * L2 + 1;       // n
    constexpr int NM  = 2 * LM + 1;       // M
    constexpr int NYM = NM * N1;
    constexpr int NCG = NM * N2 * N1;

    const int tid = threadIdx.x;
    const int il  = tid >> 5;             // warp id 0..7
    const int jl  = tid & 31;             // lane

    // Stage inputs (contiguous gmem reads, tiny). x1 duplicated into pairs,
    // row stride padded to 8 so pair loads are 16B-aligned.
    for (int k = tid; k < NCG; k += NT)     s.cg[k] = cg[k];
    for (int k = tid; k < TJ * N2; k += NT) s.x2[k] = xg2[j0 * N2 + k];
    #pragma unroll
    for (int k0 = 0; k0 < TI * N1; k0 += NT) {
        const int k = k0 + tid;
        if ((TI * N1) % NT == 0 || k < TI * N1) {
            const int row = k / N1;             // constexpr divisor -> cheap
            const int m   = k - row * N1;
            const unsigned int u = __float_as_uint(xg1[i0 * N1 + k]);
            s.x1pk[row * 8 + m] = ((unsigned long long)u << 32) | u;
        }
    }
    __syncthreads();

    // y-phase, warp-per-M: warp il computes y[:, M=il, :].
    if (il < NM) {
        float x2r[N2];
        #pragma unroll
        for (int n = 0; n < N2; n++) x2r[n] = s.x2[jl * N2 + n];
        #pragma unroll
        for (int m = 0; m < N1; m++) {
            float acc = 0.f;
            #pragma unroll
            for (int n = 0; n < N2; n++)
                acc = fmaf(s.cg[(il * N2 + n) * N1 + m], x2r[n], acc);
            s.y[jl * NYM + il * N1 + m] = acc;   // == s.y[(jl*NM+il)*N1 + m]
        }
    }
    __syncthreads();

    // Direct-store phase. Thread owns output float4 column q4 (elements
    // q4*4 .. q4*4+3 of each i-row) and iterates rows r = rb, rb+RB, ...
    constexpr int G  = 8 * NM;            // float4 per i-row (TJ*NM/4)
    constexpr int RB = NT / G;            // row stride
    const int q4 = tid % G;
    const int rb = tid / G;

    if (rb < RB) {
        // y block: contiguous [q4*4*N1, +4N1) -> N1 LDS.128, conflict-free.
        float yflat[4 * N1];
        const float4* __restrict__ yp = (const float4*)&s.y[q4 * 4 * N1];
        #pragma unroll
        for (int c = 0; c < N1; c++) {
            float4 v4 = yp[c];
            yflat[4 * c + 0] = v4.x;
            yflat[4 * c + 1] = v4.y;
            yflat[4 * c + 2] = v4.z;
            yflat[4 * c + 3] = v4.w;
        }
        // Pack: pair A = output elements (0,1), pair B = (2,3).
        unsigned long long ypkA[N1], ypkB[N1];
        #pragma unroll
        for (int m = 0; m < N1; m++) {
            ypkA[m] = pack2(yflat[0 * N1 + m], yflat[1 * N1 + m]);
            ypkB[m] = pack2(yflat[2 * N1 + m], yflat[3 * N1 + m]);
        }

        float* __restrict__ op = out + ((i0 + rb) * C + j0) * NM + q4 * 4;
        const long long step = (long long)RB * C * NM;
        const unsigned long long* __restrict__ xp0 = &s.x1pk[rb * 8];

        #pragma unroll 2
        for (int r = rb; r < TI; r += RB) {
            unsigned long long accA = 0ull, accB = 0ull;   // {0.f,0.f}
            // Pair loads: 16B-aligned LDS.128 (row base 64B-aligned).
            #pragma unroll
            for (int mp = 0; mp < N1 / 2; mp++) {
                const ulonglong2 xq = *(const ulonglong2*)&xp0[2 * mp];
                fma_f32x2(accA, xq.x, ypkA[2 * mp],     accA);
                fma_f32x2(accB, xq.x, ypkB[2 * mp],     accB);
                fma_f32x2(accA, xq.y, ypkA[2 * mp + 1], accA);
                fma_f32x2(accB, xq.y, ypkB[2 * mp + 1], accB);
            }
            {   // last (odd) m
                const unsigned long long xp = xp0[N1 - 1];
                fma_f32x2(accA, xp, ypkA[N1 - 1], accA);
                fma_f32x2(accB, xp, ypkB[N1 - 1], accB);
            }
            ulonglong2 v; v.x = accA; v.y = accB;
            *(ulonglong2*)op = v;                          // STG.128, 16B aligned
            op  += step;
            xp0 += RB * 8;
        }
    }
}

__global__ __launch_bounds__(NT, 5) void tp_kernel(Args a) {
    __shared__ Smem s;

    const int t    = c_perm[blockIdx.x >> 7];   // 128 tiles per triple, LPT order
    const int tile = blockIdx.x & 127;
    const int i0 = (tile >> 4) * TI;            // 8 i-tiles
    const int j0 = (tile & 15) * TJ;            // 16 j-tiles

    float* out = a.out + c_off[t];

    #define CASE(T, A, B, L) \
        case T: tp_impl<A, B, L>(a.x[A], a.x[B], a.cg[T], out, i0, j0, s); break;
    switch (t) {
        CASE( 0, 0, 0, 0)
        CASE( 1, 0, 1, 1)
        CASE( 2, 0, 2, 2)
        CASE( 3, 0, 3, 3)
        CASE( 4, 1, 1, 0)
        CASE( 5, 1, 1, 1)
        CASE( 6, 1, 1, 2)
        CASE( 7, 1, 2, 1)
        CASE( 8, 1, 2, 2)
        CASE( 9, 1, 2, 3)
        CASE(10, 1, 3, 2)
        CASE(11, 1, 3, 3)
        CASE(12, 2, 2, 0)
        CASE(13, 2, 2, 1)
        CASE(14, 2, 2, 2)
        CASE(15, 2, 2, 3)
        CASE(16, 2, 3, 1)
        CASE(17, 2, 3, 2)
        CASE(18, 2, 3, 3)
        CASE(19, 3, 3, 0)
        CASE(20, 3, 3, 1)
        CASE(21, 3, 3, 2)
        CASE(22, 3, 3, 3)
    }
    #undef CASE
}

extern "C" void kernel_launch(void* const* d_in, const int* in_sizes, int n_in,
                              void* d_out, int out_size) {
    Args a;
    for (int k = 0; k < 4; k++)  a.x[k]  = (const float*)d_in[k];
    for (int k = 0; k < 23; k++) a.cg[k] = (const float*)d_in[4 + k];
    a.out = (float*)d_out;

    tp_kernel<<<NTRIPLES * TILES_PER_TRIPLE, NT>>>(a);
}